// round 1
// baseline (speedup 1.0000x reference)
#include <cuda_runtime.h>
#include <cuda_bf16.h>
#include <cstdint>

#define N_NODES 50000
#define N_EDGES 600000
#define N_GRAPHS 2000
#define IN_FEATS 64
#define HIDDEN 128

// ---------------- scratch (device globals; no allocation allowed) ----------
__device__ int   g_deg_out[N_NODES];
__device__ int   g_deg_in[N_NODES];
__device__ float g_cout[N_NODES];
__device__ float g_cin[N_NODES];
__device__ float g_agg[(size_t)N_NODES * HIDDEN];
__device__ float g_x[(size_t)N_NODES * HIDDEN];
__device__ float g_y[(size_t)N_NODES * HIDDEN];
__device__ float g_gsum[(size_t)N_GRAPHS * HIDDEN];
__device__ int   g_gcnt[N_GRAPHS];

// ---------------- helpers ---------------------------------------------------
__device__ __forceinline__ void red_add_v4(float* p, float4 v) {
    asm volatile("red.global.add.v4.f32 [%0], {%1, %2, %3, %4};"
                 :: "l"(p), "f"(v.x), "f"(v.y), "f"(v.z), "f"(v.w)
                 : "memory");
}

// ---------------- zero kernels ----------------------------------------------
__global__ void zero_misc_kernel() {
    int i = blockIdx.x * blockDim.x + threadIdx.x;
    if (i < N_NODES) { g_deg_out[i] = 0; g_deg_in[i] = 0; }
    if (i < N_GRAPHS * HIDDEN) g_gsum[i] = 0.0f;
    if (i < N_GRAPHS) g_gcnt[i] = 0;
}

__global__ void zero_agg_kernel(int n4) {
    int i = blockIdx.x * blockDim.x + threadIdx.x;
    float4 z = make_float4(0.f, 0.f, 0.f, 0.f);
    for (; i < n4; i += gridDim.x * blockDim.x)
        reinterpret_cast<float4*>(g_agg)[i] = z;
}

// ---------------- degrees + coefficients -------------------------------------
__global__ void degree_kernel(const int* __restrict__ src, const int* __restrict__ dst) {
    int e = blockIdx.x * blockDim.x + threadIdx.x;
    if (e < N_EDGES) {
        atomicAdd(&g_deg_out[src[e]], 1);
        atomicAdd(&g_deg_in[dst[e]], 1);
    }
}

__global__ void coeff_kernel() {
    int i = blockIdx.x * blockDim.x + threadIdx.x;
    if (i < N_NODES) {
        g_cout[i] = rsqrtf(fmaxf((float)g_deg_out[i], 1.0f));
        g_cin[i]  = rsqrtf(fmaxf((float)g_deg_in[i], 1.0f));
    }
}

// ---------------- edge scatter: agg[dst] += x[src] * c_out[src] --------------
// F floats per node row; F/4 threads cooperate per edge; one 16B vector RED each.
template <int F>
__global__ __launch_bounds__(256)
void scatter_kernel(const float* __restrict__ x,
                    const int* __restrict__ src, const int* __restrict__ dst) {
    constexpr int TPE = F / 4;
    int tid = blockIdx.x * blockDim.x + threadIdx.x;
    int e = tid / TPE;
    int lane = tid % TPE;
    if (e >= N_EDGES) return;
    int s = src[e];
    int d = dst[e];
    float c = __ldg(&g_cout[s]);
    float4 v = __ldg(reinterpret_cast<const float4*>(x + (size_t)s * F + lane * 4));
    v.x *= c; v.y *= c; v.z *= c; v.w *= c;
    red_add_v4(g_agg + (size_t)d * F + lane * 4, v);
}

// ---------------- GEMM: C[N,128] = (agg[N,FIN] * c_in) @ W[FIN,128] + b ------
// BM=64, BN=128, BK=32. 256 threads, 8x4 register tile per thread.
template <int FIN, bool RELU>
__global__ __launch_bounds__(256)
void gemm_kernel(const float* __restrict__ A,
                 const float* __restrict__ W,
                 const float* __restrict__ bias,
                 float* __restrict__ C) {
    __shared__ float As[64][36];     // padded: float4-aligned, conflict-light
    __shared__ float Ws[32][128];

    int tid = threadIdx.x;
    int rowBase = blockIdx.x * 64;
    int r0 = (tid >> 5) * 8;         // warp id * 8  (rows)
    int c0 = (tid & 31) * 4;         // lane * 4     (cols)

    float acc[8][4];
#pragma unroll
    for (int i = 0; i < 8; i++)
#pragma unroll
        for (int j = 0; j < 4; j++) acc[i][j] = 0.f;

    for (int k0 = 0; k0 < FIN; k0 += 32) {
        // stage A tile (64x32), scaled by c_in
#pragma unroll
        for (int t = 0; t < 2; t++) {
            int p = tid + t * 256;     // 0..511
            int row = p >> 3;          // 0..63
            int k4 = p & 7;            // 0..7
            int gr = rowBase + row;
            float4 v = make_float4(0.f, 0.f, 0.f, 0.f);
            if (gr < N_NODES) {
                v = __ldg(reinterpret_cast<const float4*>(
                        A + (size_t)gr * FIN + k0 + k4 * 4));
                float c = __ldg(&g_cin[gr]);
                v.x *= c; v.y *= c; v.z *= c; v.w *= c;
            }
            *reinterpret_cast<float4*>(&As[row][k4 * 4]) = v;
        }
        // stage W tile (32x128)
#pragma unroll
        for (int t = 0; t < 4; t++) {
            int p = tid + t * 256;     // 0..1023
            int k = p >> 5;            // 0..31
            int c4 = p & 31;           // 0..31
            *reinterpret_cast<float4*>(&Ws[k][c4 * 4]) =
                __ldg(reinterpret_cast<const float4*>(
                    W + (size_t)(k0 + k) * 128 + c4 * 4));
        }
        __syncthreads();

#pragma unroll
        for (int kk = 0; kk < 32; kk++) {
            float w0 = Ws[kk][c0 + 0];
            float w1 = Ws[kk][c0 + 1];
            float w2 = Ws[kk][c0 + 2];
            float w3 = Ws[kk][c0 + 3];
#pragma unroll
            for (int i = 0; i < 8; i++) {
                float a = As[r0 + i][kk];     // broadcast within warp
                acc[i][0] = fmaf(a, w0, acc[i][0]);
                acc[i][1] = fmaf(a, w1, acc[i][1]);
                acc[i][2] = fmaf(a, w2, acc[i][2]);
                acc[i][3] = fmaf(a, w3, acc[i][3]);
            }
        }
        __syncthreads();
    }

    float b0 = bias[c0 + 0], b1 = bias[c0 + 1], b2 = bias[c0 + 2], b3 = bias[c0 + 3];
#pragma unroll
    for (int i = 0; i < 8; i++) {
        int gr = rowBase + r0 + i;
        if (gr < N_NODES) {
            float4 v;
            v.x = acc[i][0] + b0;
            v.y = acc[i][1] + b1;
            v.z = acc[i][2] + b2;
            v.w = acc[i][3] + b3;
            if (RELU) {
                v.x = fmaxf(v.x, 0.f); v.y = fmaxf(v.y, 0.f);
                v.z = fmaxf(v.z, 0.f); v.w = fmaxf(v.w, 0.f);
            }
            *reinterpret_cast<float4*>(C + (size_t)gr * 128 + c0) = v;
        }
    }
}

// ---------------- graph mean-pool accumulation ------------------------------
__global__ __launch_bounds__(256)
void pool_kernel(const float* __restrict__ y, const int* __restrict__ gid) {
    int t = blockIdx.x * blockDim.x + threadIdx.x;
    int node = t >> 5;
    int lane = t & 31;
    if (node >= N_NODES) return;
    int g = __ldg(&gid[node]);
    float4 v = __ldg(reinterpret_cast<const float4*>(y + (size_t)node * 128 + lane * 4));
    red_add_v4(g_gsum + (size_t)g * 128 + lane * 4, v);
    if (lane == 0) atomicAdd(&g_gcnt[g], 1);
}

// ---------------- fused MLP head (16 graphs per block) -----------------------
__global__ __launch_bounds__(256)
void mlp_kernel(const float* __restrict__ fg,
                const float* __restrict__ Wl1, const float* __restrict__ bl1,
                const float* __restrict__ Wl2, const float* __restrict__ bl2,
                const float* __restrict__ Wl3, const float* __restrict__ bl3,
                float* __restrict__ out) {
    __shared__ float in_s[16][132];   // 131 used
    __shared__ float h_s[16][256];

    int tid = threadIdx.x;
    int gBase = blockIdx.x * 16;

    // build inputs: mean pooled features + 3 graph features
    for (int idx = tid; idx < 16 * 128; idx += 256) {
        int gl = idx >> 7, f = idx & 127;
        int g = gBase + gl;
        float c = (float)g_gcnt[g];
        in_s[gl][f] = g_gsum[(size_t)g * 128 + f] / fmaxf(c, 1.0f);
    }
    for (int idx = tid; idx < 16 * 3; idx += 256) {
        int gl = idx / 3, f = idx % 3;
        in_s[gl][128 + f] = fg[(size_t)(gBase + gl) * 3 + f];
    }
    __syncthreads();

    float acc[16];
    // layer 1: 131 -> 256
    {
        float b = bl1[tid];
#pragma unroll
        for (int g = 0; g < 16; g++) acc[g] = b;
        for (int i = 0; i < 131; i++) {
            float w = __ldg(&Wl1[(size_t)i * 256 + tid]);
#pragma unroll
            for (int g = 0; g < 16; g++) acc[g] = fmaf(in_s[g][i], w, acc[g]);
        }
#pragma unroll
        for (int g = 0; g < 16; g++) h_s[g][tid] = fmaxf(acc[g], 0.f);
    }
    __syncthreads();
    // layer 2: 256 -> 256
    {
        float b = bl2[tid];
#pragma unroll
        for (int g = 0; g < 16; g++) acc[g] = b;
        for (int i = 0; i < 256; i++) {
            float w = __ldg(&Wl2[(size_t)i * 256 + tid]);
#pragma unroll
            for (int g = 0; g < 16; g++) acc[g] = fmaf(h_s[g][i], w, acc[g]);
        }
        __syncthreads();
#pragma unroll
        for (int g = 0; g < 16; g++) h_s[g][tid] = fmaxf(acc[g], 0.f);
    }
    __syncthreads();
    // layer 3: 256 -> 1 (16 threads per graph)
    {
        int g = tid >> 4;
        int lane = tid & 15;
        float s = 0.f;
        for (int j = lane; j < 256; j += 16) s += h_s[g][j] * __ldg(&Wl3[j]);
#pragma unroll
        for (int off = 8; off > 0; off >>= 1)
            s += __shfl_down_sync(0xFFFFFFFFu, s, off, 16);
        if (lane == 0) out[gBase + g] = s + bl3[0];
    }
}

// ---------------- launch -----------------------------------------------------
extern "C" void kernel_launch(void* const* d_in, const int* in_sizes, int n_in,
                              void* d_out, int out_size) {
    const float* feats_node  = (const float*)d_in[0];
    const float* feats_graph = (const float*)d_in[1];
    const float* W1 = (const float*)d_in[2];
    const float* b1 = (const float*)d_in[3];
    const float* W2 = (const float*)d_in[4];
    const float* b2 = (const float*)d_in[5];
    const float* W3 = (const float*)d_in[6];
    const float* b3 = (const float*)d_in[7];
    const float* Wl1 = (const float*)d_in[8];
    const float* bl1 = (const float*)d_in[9];
    const float* Wl2 = (const float*)d_in[10];
    const float* bl2 = (const float*)d_in[11];
    const float* Wl3 = (const float*)d_in[12];
    const float* bl3 = (const float*)d_in[13];
    const int* src = (const int*)d_in[14];
    const int* dst = (const int*)d_in[15];
    const int* gid = (const int*)d_in[16];
    float* out = (float*)d_out;

    // device addresses of scratch globals (host API, not a stream op)
    void *p_agg, *p_x, *p_y;
    cudaGetSymbolAddress(&p_agg, g_agg);
    cudaGetSymbolAddress(&p_x, g_x);
    cudaGetSymbolAddress(&p_y, g_y);
    float* agg = (float*)p_agg;
    float* xb  = (float*)p_x;
    float* yb  = (float*)p_y;

    // degrees + normalization coeffs + misc zeroing
    zero_misc_kernel<<<(N_GRAPHS * HIDDEN + 255) / 256, 256>>>();
    degree_kernel<<<(N_EDGES + 255) / 256, 256>>>(src, dst);
    coeff_kernel<<<(N_NODES + 255) / 256, 256>>>();

    const int gemm_blocks = (N_NODES + 63) / 64;

    // ---- layer 1: 64-wide aggregate, GEMM 64->128, relu ----
    zero_agg_kernel<<<2048, 256>>>(N_NODES * IN_FEATS / 4);
    {
        int threads = N_EDGES * (IN_FEATS / 4);
        scatter_kernel<IN_FEATS><<<(threads + 255) / 256, 256>>>(feats_node, src, dst);
    }
    gemm_kernel<IN_FEATS, true><<<gemm_blocks, 256>>>(agg, W1, b1, xb);

    // ---- layer 2: 128-wide aggregate, GEMM 128->128, relu ----
    zero_agg_kernel<<<2048, 256>>>(N_NODES * HIDDEN / 4);
    {
        int threads = N_EDGES * (HIDDEN / 4);
        scatter_kernel<HIDDEN><<<(threads + 255) / 256, 256>>>(xb, src, dst);
    }
    gemm_kernel<HIDDEN, true><<<gemm_blocks, 256>>>(agg, W2, b2, yb);

    // ---- layer 3: 128-wide aggregate, GEMM 128->128, no relu ----
    zero_agg_kernel<<<2048, 256>>>(N_NODES * HIDDEN / 4);
    {
        int threads = N_EDGES * (HIDDEN / 4);
        scatter_kernel<HIDDEN><<<(threads + 255) / 256, 256>>>(yb, src, dst);
    }
    gemm_kernel<HIDDEN, false><<<gemm_blocks, 256>>>(agg, W3, b3, xb);

    // ---- readout + MLP head ----
    pool_kernel<<<(N_NODES * 32 + 255) / 256, 256>>>(xb, gid);
    mlp_kernel<<<N_GRAPHS / 16, 256>>>(feats_graph, Wl1, bl1, Wl2, bl2, Wl3, bl3, out);
}

// round 2
// speedup vs baseline: 2.0177x; 2.0177x over previous
#include <cuda_runtime.h>
#include <cuda_bf16.h>
#include <cstdint>

#define N_NODES 50000
#define N_EDGES 600000
#define N_GRAPHS 2000
#define IN_FEATS 64
#define HIDDEN 128
#define SCAN_BS 1024
#define SCAN_NB ((N_NODES + SCAN_BS - 1) / SCAN_BS)   // 49

// ---------------- scratch (device globals; no allocation allowed) ----------
__device__ int   g_deg_out[N_NODES];
__device__ int   g_deg_in[N_NODES];
__device__ float g_cout[N_NODES];
__device__ float g_cin[N_NODES];
__device__ int   g_rowstart[N_NODES + 1];
__device__ int   g_fill[N_NODES];
__device__ int   g_blocksums[SCAN_NB];
__device__ int   g_blockoff[SCAN_NB];
__device__ int   g_csr_src[N_EDGES];
__device__ float g_agg[(size_t)N_NODES * HIDDEN];
__device__ float g_x[(size_t)N_NODES * HIDDEN];
__device__ float g_y[(size_t)N_NODES * HIDDEN];
__device__ float g_gsum[(size_t)N_GRAPHS * HIDDEN];
__device__ int   g_gcnt[N_GRAPHS];

// ---------------- helpers ---------------------------------------------------
__device__ __forceinline__ void red_add_v4(float* p, float4 v) {
    asm volatile("red.global.add.v4.f32 [%0], {%1, %2, %3, %4};"
                 :: "l"(p), "f"(v.x), "f"(v.y), "f"(v.z), "f"(v.w)
                 : "memory");
}

// ---------------- zero / degree / coeff ---------------------------------------
__global__ void zero_misc_kernel() {
    int i = blockIdx.x * blockDim.x + threadIdx.x;
    if (i < N_NODES) { g_deg_out[i] = 0; g_deg_in[i] = 0; }
    if (i < N_GRAPHS * HIDDEN) g_gsum[i] = 0.0f;
    if (i < N_GRAPHS) g_gcnt[i] = 0;
}

__global__ void degree_kernel(const int* __restrict__ src, const int* __restrict__ dst) {
    int e = blockIdx.x * blockDim.x + threadIdx.x;
    if (e < N_EDGES) {
        atomicAdd(&g_deg_out[src[e]], 1);
        atomicAdd(&g_deg_in[dst[e]], 1);
    }
}

__global__ void coeff_gcnt_kernel(const int* __restrict__ gid) {
    int i = blockIdx.x * blockDim.x + threadIdx.x;
    if (i < N_NODES) {
        g_cout[i] = rsqrtf(fmaxf((float)g_deg_out[i], 1.0f));
        g_cin[i]  = rsqrtf(fmaxf((float)g_deg_in[i], 1.0f));
        atomicAdd(&g_gcnt[gid[i]], 1);
    }
}

// ---------------- CSR build: exclusive scan of deg_in + fill -----------------
__global__ __launch_bounds__(SCAN_BS)
void scan_block_kernel() {
    int i = blockIdx.x * SCAN_BS + threadIdx.x;
    int lane = threadIdx.x & 31, wid = threadIdx.x >> 5;
    int v = (i < N_NODES) ? g_deg_in[i] : 0;
    int x = v;
#pragma unroll
    for (int o = 1; o < 32; o <<= 1) {
        int y = __shfl_up_sync(0xFFFFFFFFu, x, o);
        if (lane >= o) x += y;
    }
    __shared__ int wsum[32];
    if (lane == 31) wsum[wid] = x;
    __syncthreads();
    if (wid == 0) {
        int w = wsum[lane];
#pragma unroll
        for (int o = 1; o < 32; o <<= 1) {
            int y = __shfl_up_sync(0xFFFFFFFFu, w, o);
            if (lane >= o) w += y;
        }
        wsum[lane] = w;
    }
    __syncthreads();
    int excl = x - v + (wid > 0 ? wsum[wid - 1] : 0);
    if (i < N_NODES) g_rowstart[i] = excl;
    if (threadIdx.x == 0) g_blocksums[blockIdx.x] = wsum[31];
}

__global__ void scan_sums_kernel() {   // 1 block, 32 threads; SCAN_NB <= 64
    int lane = threadIdx.x;
    int v0 = (lane < SCAN_NB) ? g_blocksums[lane] : 0;
    int v1 = (lane + 32 < SCAN_NB) ? g_blocksums[lane + 32] : 0;
    int x = v0;
#pragma unroll
    for (int o = 1; o < 32; o <<= 1) {
        int y = __shfl_up_sync(0xFFFFFFFFu, x, o);
        if (lane >= o) x += y;
    }
    int total0 = __shfl_sync(0xFFFFFFFFu, x, 31);
    int z = v1;
#pragma unroll
    for (int o = 1; o < 32; o <<= 1) {
        int y = __shfl_up_sync(0xFFFFFFFFu, z, o);
        if (lane >= o) z += y;
    }
    z += total0;
    if (lane < SCAN_NB) g_blockoff[lane] = x - v0;
    if (lane + 32 < SCAN_NB) g_blockoff[lane + 32] = z - v1;
}

__global__ __launch_bounds__(SCAN_BS)
void scan_add_kernel() {
    int i = blockIdx.x * SCAN_BS + threadIdx.x;
    if (i < N_NODES) {
        int r = g_rowstart[i] + g_blockoff[blockIdx.x];
        g_rowstart[i] = r;
        g_fill[i] = r;
    }
    if (i == 0) g_rowstart[N_NODES] = N_EDGES;
}

__global__ void fill_kernel(const int* __restrict__ src, const int* __restrict__ dst) {
    int e = blockIdx.x * blockDim.x + threadIdx.x;
    if (e < N_EDGES) {
        int pos = atomicAdd(&g_fill[dst[e]], 1);
        g_csr_src[pos] = src[e];
    }
}

// ---------------- pull aggregation: agg[d] = c_in[d] * sum_{s in N(d)} x[s](*c_out[s]?)
// F=128: 32 lanes/node (float4 per lane). F=64: 16 lanes/node.
template <int F, bool SCALE_COUT>
__global__ __launch_bounds__(256)
void pull_kernel(const float* __restrict__ x) {
    constexpr int LPN = F / 4;                 // lanes per node
    int t = blockIdx.x * blockDim.x + threadIdx.x;
    int node = t / LPN;
    int lane = t % LPN;
    if (node >= N_NODES) return;
    int j = g_rowstart[node];
    int end = g_rowstart[node + 1];
    float4 acc = make_float4(0.f, 0.f, 0.f, 0.f);
    for (; j + 1 < end; j += 2) {
        int s0 = __ldg(&g_csr_src[j]);
        int s1 = __ldg(&g_csr_src[j + 1]);
        float4 v0 = __ldg(reinterpret_cast<const float4*>(x + (size_t)s0 * F + lane * 4));
        float4 v1 = __ldg(reinterpret_cast<const float4*>(x + (size_t)s1 * F + lane * 4));
        float c0 = SCALE_COUT ? __ldg(&g_cout[s0]) : 1.0f;
        float c1 = SCALE_COUT ? __ldg(&g_cout[s1]) : 1.0f;
        acc.x = fmaf(v0.x, c0, acc.x); acc.y = fmaf(v0.y, c0, acc.y);
        acc.z = fmaf(v0.z, c0, acc.z); acc.w = fmaf(v0.w, c0, acc.w);
        acc.x = fmaf(v1.x, c1, acc.x); acc.y = fmaf(v1.y, c1, acc.y);
        acc.z = fmaf(v1.z, c1, acc.z); acc.w = fmaf(v1.w, c1, acc.w);
    }
    if (j < end) {
        int s0 = __ldg(&g_csr_src[j]);
        float4 v0 = __ldg(reinterpret_cast<const float4*>(x + (size_t)s0 * F + lane * 4));
        float c0 = SCALE_COUT ? __ldg(&g_cout[s0]) : 1.0f;
        acc.x = fmaf(v0.x, c0, acc.x); acc.y = fmaf(v0.y, c0, acc.y);
        acc.z = fmaf(v0.z, c0, acc.z); acc.w = fmaf(v0.w, c0, acc.w);
    }
    float ci = __ldg(&g_cin[node]);
    acc.x *= ci; acc.y *= ci; acc.z *= ci; acc.w *= ci;
    *reinterpret_cast<float4*>(g_agg + (size_t)node * F + lane * 4) = acc;
}

// ---------------- GEMM: C[N,128] = A[N,FIN] @ W[FIN,128] + b -----------------
// BM=64, BN=128, BK=32. 256 threads, 8x4 register tile per thread.
// RELU: apply relu. SCALE_OUT: multiply output row by c_out[row] (pre-scale for
// next layer's pull). POOL: instead of storing C, RED rows into g_gsum[gid].
template <int FIN, bool RELU, bool SCALE_OUT, bool POOL>
__global__ __launch_bounds__(256)
void gemm_kernel(const float* __restrict__ A,
                 const float* __restrict__ W,
                 const float* __restrict__ bias,
                 float* __restrict__ C,
                 const int* __restrict__ gid) {
    __shared__ float As[64][36];
    __shared__ float Ws[32][128];

    int tid = threadIdx.x;
    int rowBase = blockIdx.x * 64;
    int r0 = (tid >> 5) * 8;
    int c0 = (tid & 31) * 4;

    float acc[8][4];
#pragma unroll
    for (int i = 0; i < 8; i++)
#pragma unroll
        for (int j = 0; j < 4; j++) acc[i][j] = 0.f;

    for (int k0 = 0; k0 < FIN; k0 += 32) {
#pragma unroll
        for (int t = 0; t < 2; t++) {
            int p = tid + t * 256;
            int row = p >> 3;
            int k4 = p & 7;
            int gr = rowBase + row;
            float4 v = make_float4(0.f, 0.f, 0.f, 0.f);
            if (gr < N_NODES)
                v = __ldg(reinterpret_cast<const float4*>(A + (size_t)gr * FIN + k0 + k4 * 4));
            *reinterpret_cast<float4*>(&As[row][k4 * 4]) = v;
        }
#pragma unroll
        for (int t = 0; t < 4; t++) {
            int p = tid + t * 256;
            int k = p >> 5;
            int c4 = p & 31;
            *reinterpret_cast<float4*>(&Ws[k][c4 * 4]) =
                __ldg(reinterpret_cast<const float4*>(W + (size_t)(k0 + k) * 128 + c4 * 4));
        }
        __syncthreads();

#pragma unroll
        for (int kk = 0; kk < 32; kk++) {
            float w0 = Ws[kk][c0 + 0];
            float w1 = Ws[kk][c0 + 1];
            float w2 = Ws[kk][c0 + 2];
            float w3 = Ws[kk][c0 + 3];
#pragma unroll
            for (int i = 0; i < 8; i++) {
                float a = As[r0 + i][kk];
                acc[i][0] = fmaf(a, w0, acc[i][0]);
                acc[i][1] = fmaf(a, w1, acc[i][1]);
                acc[i][2] = fmaf(a, w2, acc[i][2]);
                acc[i][3] = fmaf(a, w3, acc[i][3]);
            }
        }
        __syncthreads();
    }

    float b0 = bias[c0 + 0], b1 = bias[c0 + 1], b2 = bias[c0 + 2], b3 = bias[c0 + 3];
#pragma unroll
    for (int i = 0; i < 8; i++) {
        int gr = rowBase + r0 + i;
        if (gr < N_NODES) {
            float4 v;
            v.x = acc[i][0] + b0;
            v.y = acc[i][1] + b1;
            v.z = acc[i][2] + b2;
            v.w = acc[i][3] + b3;
            if (RELU) {
                v.x = fmaxf(v.x, 0.f); v.y = fmaxf(v.y, 0.f);
                v.z = fmaxf(v.z, 0.f); v.w = fmaxf(v.w, 0.f);
            }
            if (SCALE_OUT) {
                float co = __ldg(&g_cout[gr]);
                v.x *= co; v.y *= co; v.z *= co; v.w *= co;
            }
            if (POOL) {
                int g = __ldg(&gid[gr]);
                red_add_v4(g_gsum + (size_t)g * 128 + c0, v);
            } else {
                *reinterpret_cast<float4*>(C + (size_t)gr * 128 + c0) = v;
            }
        }
    }
}

// ---------------- fused MLP head (16 graphs per block) -----------------------
__global__ __launch_bounds__(256)
void mlp_kernel(const float* __restrict__ fg,
                const float* __restrict__ Wl1, const float* __restrict__ bl1,
                const float* __restrict__ Wl2, const float* __restrict__ bl2,
                const float* __restrict__ Wl3, const float* __restrict__ bl3,
                float* __restrict__ out) {
    __shared__ float in_s[16][132];
    __shared__ float h_s[16][256];

    int tid = threadIdx.x;
    int gBase = blockIdx.x * 16;

    for (int idx = tid; idx < 16 * 128; idx += 256) {
        int gl = idx >> 7, f = idx & 127;
        int g = gBase + gl;
        float c = (float)g_gcnt[g];
        in_s[gl][f] = g_gsum[(size_t)g * 128 + f] / fmaxf(c, 1.0f);
    }
    for (int idx = tid; idx < 16 * 3; idx += 256) {
        int gl = idx / 3, f = idx % 3;
        in_s[gl][128 + f] = fg[(size_t)(gBase + gl) * 3 + f];
    }
    __syncthreads();

    float acc[16];
    {
        float b = bl1[tid];
#pragma unroll
        for (int g = 0; g < 16; g++) acc[g] = b;
        for (int i = 0; i < 131; i++) {
            float w = __ldg(&Wl1[(size_t)i * 256 + tid]);
#pragma unroll
            for (int g = 0; g < 16; g++) acc[g] = fmaf(in_s[g][i], w, acc[g]);
        }
#pragma unroll
        for (int g = 0; g < 16; g++) h_s[g][tid] = fmaxf(acc[g], 0.f);
    }
    __syncthreads();
    {
        float b = bl2[tid];
#pragma unroll
        for (int g = 0; g < 16; g++) acc[g] = b;
        for (int i = 0; i < 256; i++) {
            float w = __ldg(&Wl2[(size_t)i * 256 + tid]);
#pragma unroll
            for (int g = 0; g < 16; g++) acc[g] = fmaf(h_s[g][i], w, acc[g]);
        }
        __syncthreads();
#pragma unroll
        for (int g = 0; g < 16; g++) h_s[g][tid] = fmaxf(acc[g], 0.f);
    }
    __syncthreads();
    {
        int g = tid >> 4;
        int lane = tid & 15;
        float s = 0.f;
        for (int j = lane; j < 256; j += 16) s += h_s[g][j] * __ldg(&Wl3[j]);
#pragma unroll
        for (int off = 8; off > 0; off >>= 1)
            s += __shfl_down_sync(0xFFFFFFFFu, s, off, 16);
        if (lane == 0) out[gBase + g] = s + bl3[0];
    }
}

// ---------------- launch -----------------------------------------------------
extern "C" void kernel_launch(void* const* d_in, const int* in_sizes, int n_in,
                              void* d_out, int out_size) {
    const float* feats_node  = (const float*)d_in[0];
    const float* feats_graph = (const float*)d_in[1];
    const float* W1 = (const float*)d_in[2];
    const float* b1 = (const float*)d_in[3];
    const float* W2 = (const float*)d_in[4];
    const float* b2 = (const float*)d_in[5];
    const float* W3 = (const float*)d_in[6];
    const float* b3 = (const float*)d_in[7];
    const float* Wl1 = (const float*)d_in[8];
    const float* bl1 = (const float*)d_in[9];
    const float* Wl2 = (const float*)d_in[10];
    const float* bl2 = (const float*)d_in[11];
    const float* Wl3 = (const float*)d_in[12];
    const float* bl3 = (const float*)d_in[13];
    const int* src = (const int*)d_in[14];
    const int* dst = (const int*)d_in[15];
    const int* gid = (const int*)d_in[16];
    float* out = (float*)d_out;

    void *p_agg, *p_x, *p_y;
    cudaGetSymbolAddress(&p_agg, g_agg);
    cudaGetSymbolAddress(&p_x, g_x);
    cudaGetSymbolAddress(&p_y, g_y);
    float* agg = (float*)p_agg;
    float* xb  = (float*)p_x;
    float* yb  = (float*)p_y;

    // --- graph preprocessing: degrees, coeffs, CSR by dst ---
    zero_misc_kernel<<<(N_GRAPHS * HIDDEN + 255) / 256, 256>>>();
    degree_kernel<<<(N_EDGES + 255) / 256, 256>>>(src, dst);
    scan_block_kernel<<<SCAN_NB, SCAN_BS>>>();
    scan_sums_kernel<<<1, 32>>>();
    scan_add_kernel<<<SCAN_NB, SCAN_BS>>>();
    coeff_gcnt_kernel<<<(N_NODES + 255) / 256, 256>>>(gid);
    fill_kernel<<<(N_EDGES + 255) / 256, 256>>>(src, dst);

    const int gemm_blocks = (N_NODES + 63) / 64;

    // ---- layer 1: pull (c_out applied per edge), GEMM 64->128, relu, *c_out
    pull_kernel<IN_FEATS, true><<<(N_NODES * (IN_FEATS / 4) + 255) / 256, 256>>>(feats_node);
    gemm_kernel<IN_FEATS, true, true, false><<<gemm_blocks, 256>>>(agg, W1, b1, xb, gid);

    // ---- layer 2: pull (input pre-scaled), GEMM 128->128, relu, *c_out
    pull_kernel<HIDDEN, false><<<(N_NODES * (HIDDEN / 4) + 255) / 256, 256>>>(xb);
    gemm_kernel<HIDDEN, true, true, false><<<gemm_blocks, 256>>>(agg, W2, b2, yb, gid);

    // ---- layer 3: pull, GEMM 128->128 (no relu), fused mean-pool RED
    pull_kernel<HIDDEN, false><<<(N_NODES * (HIDDEN / 4) + 255) / 256, 256>>>(yb);
    gemm_kernel<HIDDEN, false, false, true><<<gemm_blocks, 256>>>(agg, W3, b3, nullptr, gid);

    // ---- MLP head ----
    mlp_kernel<<<N_GRAPHS / 16, 256>>>(feats_graph, Wl1, bl1, Wl2, bl2, Wl3, bl3, out);
}

// round 3
// speedup vs baseline: 2.1419x; 1.0615x over previous
#include <cuda_runtime.h>
#include <cuda_bf16.h>
#include <cstdint>

#define N_NODES 50000
#define N_EDGES 600000
#define N_GRAPHS 2000
#define IN_FEATS 64
#define HIDDEN 128
#define SCAN_BS 1024
#define SCAN_NB ((N_NODES + SCAN_BS - 1) / SCAN_BS)   // 49

typedef unsigned long long u64;

// ---------------- scratch (device globals; no allocation allowed) ----------
__device__ int   g_deg_out[N_NODES];
__device__ int   g_deg_in[N_NODES];
__device__ float g_cout[N_NODES];
__device__ float g_cin[N_NODES];
__device__ int   g_rowstart[N_NODES + 1];
__device__ int   g_fill[N_NODES];
__device__ int   g_blocksums[SCAN_NB];
__device__ int   g_blockoff[SCAN_NB];
__device__ int   g_csr_src[N_EDGES];
__device__ float g_agg[(size_t)N_NODES * HIDDEN];
__device__ float g_x[(size_t)N_NODES * HIDDEN];
__device__ float g_y[(size_t)N_NODES * HIDDEN];
__device__ float g_gsum[(size_t)N_GRAPHS * HIDDEN];
__device__ int   g_gcnt[N_GRAPHS];

// ---------------- helpers ---------------------------------------------------
__device__ __forceinline__ void red_add_v4(float* p, float4 v) {
    asm volatile("red.global.add.v4.f32 [%0], {%1, %2, %3, %4};"
                 :: "l"(p), "f"(v.x), "f"(v.y), "f"(v.z), "f"(v.w)
                 : "memory");
}
__device__ __forceinline__ u64 pack2(float lo, float hi) {
    u64 r; asm("mov.b64 %0, {%1, %2};" : "=l"(r) : "f"(lo), "f"(hi)); return r;
}
__device__ __forceinline__ u64 fma2(u64 a, u64 b, u64 c) {
    u64 d; asm("fma.rn.f32x2 %0, %1, %2, %3;" : "=l"(d) : "l"(a), "l"(b), "l"(c)); return d;
}
__device__ __forceinline__ float2 unpack2(u64 v) {
    float2 f; asm("mov.b64 {%0, %1}, %2;" : "=f"(f.x), "=f"(f.y) : "l"(v)); return f;
}

// ---------------- zero / degree -----------------------------------------------
__global__ void zero_misc_kernel() {
    int i = blockIdx.x * blockDim.x + threadIdx.x;
    if (i < N_NODES) { g_deg_out[i] = 0; g_deg_in[i] = 0; }
    if (i < N_GRAPHS * HIDDEN) g_gsum[i] = 0.0f;
    if (i < N_GRAPHS) g_gcnt[i] = 0;
}

__global__ void degree_kernel(const int* __restrict__ src, const int* __restrict__ dst) {
    int e = blockIdx.x * blockDim.x + threadIdx.x;
    if (e < N_EDGES) {
        atomicAdd(&g_deg_out[src[e]], 1);
        atomicAdd(&g_deg_in[dst[e]], 1);
    }
}

// ---------------- CSR build: exclusive scan of deg_in + fill -----------------
__global__ __launch_bounds__(SCAN_BS)
void scan_block_kernel() {
    int i = blockIdx.x * SCAN_BS + threadIdx.x;
    int lane = threadIdx.x & 31, wid = threadIdx.x >> 5;
    int v = (i < N_NODES) ? g_deg_in[i] : 0;
    int x = v;
#pragma unroll
    for (int o = 1; o < 32; o <<= 1) {
        int y = __shfl_up_sync(0xFFFFFFFFu, x, o);
        if (lane >= o) x += y;
    }
    __shared__ int wsum[32];
    if (lane == 31) wsum[wid] = x;
    __syncthreads();
    if (wid == 0) {
        int w = wsum[lane];
#pragma unroll
        for (int o = 1; o < 32; o <<= 1) {
            int y = __shfl_up_sync(0xFFFFFFFFu, w, o);
            if (lane >= o) w += y;
        }
        wsum[lane] = w;
    }
    __syncthreads();
    int excl = x - v + (wid > 0 ? wsum[wid - 1] : 0);
    if (i < N_NODES) g_rowstart[i] = excl;
    if (threadIdx.x == 0) g_blocksums[blockIdx.x] = wsum[31];
}

__global__ void scan_sums_kernel() {   // 1 block, 32 threads; SCAN_NB <= 64
    int lane = threadIdx.x;
    int v0 = (lane < SCAN_NB) ? g_blocksums[lane] : 0;
    int v1 = (lane + 32 < SCAN_NB) ? g_blocksums[lane + 32] : 0;
    int x = v0;
#pragma unroll
    for (int o = 1; o < 32; o <<= 1) {
        int y = __shfl_up_sync(0xFFFFFFFFu, x, o);
        if (lane >= o) x += y;
    }
    int total0 = __shfl_sync(0xFFFFFFFFu, x, 31);
    int z = v1;
#pragma unroll
    for (int o = 1; o < 32; o <<= 1) {
        int y = __shfl_up_sync(0xFFFFFFFFu, z, o);
        if (lane >= o) z += y;
    }
    z += total0;
    if (lane < SCAN_NB) g_blockoff[lane] = x - v0;
    if (lane + 32 < SCAN_NB) g_blockoff[lane + 32] = z - v1;
}

// finalize rowstart + fill cursors + normalization coeffs + graph counts
__global__ __launch_bounds__(SCAN_BS)
void scan_add_coeff_kernel(const int* __restrict__ gid) {
    int i = blockIdx.x * SCAN_BS + threadIdx.x;
    if (i < N_NODES) {
        int r = g_rowstart[i] + g_blockoff[blockIdx.x];
        g_rowstart[i] = r;
        g_fill[i] = r;
        g_cout[i] = rsqrtf(fmaxf((float)g_deg_out[i], 1.0f));
        g_cin[i]  = rsqrtf(fmaxf((float)g_deg_in[i], 1.0f));
        atomicAdd(&g_gcnt[gid[i]], 1);
    }
    if (i == 0) g_rowstart[N_NODES] = N_EDGES;
}

__global__ void fill_kernel(const int* __restrict__ src, const int* __restrict__ dst) {
    int e = blockIdx.x * blockDim.x + threadIdx.x;
    if (e < N_EDGES) {
        int pos = atomicAdd(&g_fill[dst[e]], 1);
        g_csr_src[pos] = src[e];
    }
}

// ---------------- pull aggregation: agg[d] = c_in[d] * sum_{s in N(d)} x[s](*c_out[s]?)
template <int F, bool SCALE_COUT>
__global__ __launch_bounds__(256)
void pull_kernel(const float* __restrict__ x) {
    constexpr int LPN = F / 4;                 // lanes per node
    int t = blockIdx.x * blockDim.x + threadIdx.x;
    int node = t / LPN;
    int lane = t % LPN;
    if (node >= N_NODES) return;
    int j = g_rowstart[node];
    int end = g_rowstart[node + 1];
    float4 acc = make_float4(0.f, 0.f, 0.f, 0.f);
    for (; j + 1 < end; j += 2) {
        int s0 = __ldg(&g_csr_src[j]);
        int s1 = __ldg(&g_csr_src[j + 1]);
        float4 v0 = __ldg(reinterpret_cast<const float4*>(x + (size_t)s0 * F + lane * 4));
        float4 v1 = __ldg(reinterpret_cast<const float4*>(x + (size_t)s1 * F + lane * 4));
        float c0 = SCALE_COUT ? __ldg(&g_cout[s0]) : 1.0f;
        float c1 = SCALE_COUT ? __ldg(&g_cout[s1]) : 1.0f;
        acc.x = fmaf(v0.x, c0, acc.x); acc.y = fmaf(v0.y, c0, acc.y);
        acc.z = fmaf(v0.z, c0, acc.z); acc.w = fmaf(v0.w, c0, acc.w);
        acc.x = fmaf(v1.x, c1, acc.x); acc.y = fmaf(v1.y, c1, acc.y);
        acc.z = fmaf(v1.z, c1, acc.z); acc.w = fmaf(v1.w, c1, acc.w);
    }
    if (j < end) {
        int s0 = __ldg(&g_csr_src[j]);
        float4 v0 = __ldg(reinterpret_cast<const float4*>(x + (size_t)s0 * F + lane * 4));
        float c0 = SCALE_COUT ? __ldg(&g_cout[s0]) : 1.0f;
        acc.x = fmaf(v0.x, c0, acc.x); acc.y = fmaf(v0.y, c0, acc.y);
        acc.z = fmaf(v0.z, c0, acc.z); acc.w = fmaf(v0.w, c0, acc.w);
    }
    float ci = __ldg(&g_cin[node]);
    acc.x *= ci; acc.y *= ci; acc.z *= ci; acc.w *= ci;
    *reinterpret_cast<float4*>(g_agg + (size_t)node * F + lane * 4) = acc;
}

// ---------------- GEMM (packed f32x2): C[N,128] = A[N,FIN] @ W[FIN,128] + b --
// BM=64, BN=128, BK=32. 256 threads. Each thread: 4 row-pairs x 4 cols packed.
template <int FIN, bool RELU, bool SCALE_OUT, bool POOL>
__global__ __launch_bounds__(256)
void gemm_kernel(const float* __restrict__ A,
                 const float* __restrict__ W,
                 const float* __restrict__ bias,
                 float* __restrict__ C,
                 const int* __restrict__ gid) {
    __shared__ float At[32][66];     // k-major A tile: [kk][row], 64 rows + pad
    __shared__ float Ws[32][128];

    int tid = threadIdx.x;
    int rowBase = blockIdx.x * 64;
    int r0 = (tid >> 5) * 8;         // warp id * 8  (rows)
    int c0 = (tid & 31) * 4;         // lane * 4     (cols)

    u64 acc[4][4];                   // [row pair][col]
#pragma unroll
    for (int p = 0; p < 4; p++)
#pragma unroll
        for (int j = 0; j < 4; j++) acc[p][j] = 0ull;   // two packed 0.0f

    for (int k0 = 0; k0 < FIN; k0 += 32) {
        // stage A tile (64 rows x 32 k) transposed into At[k][row]
#pragma unroll
        for (int t = 0; t < 2; t++) {
            int p = tid + t * 256;     // 0..511
            int row = p >> 3;          // 0..63
            int k4 = p & 7;            // 0..7
            int gr = rowBase + row;
            float4 v = make_float4(0.f, 0.f, 0.f, 0.f);
            if (gr < N_NODES)
                v = __ldg(reinterpret_cast<const float4*>(A + (size_t)gr * FIN + k0 + k4 * 4));
            At[k4 * 4 + 0][row] = v.x;
            At[k4 * 4 + 1][row] = v.y;
            At[k4 * 4 + 2][row] = v.z;
            At[k4 * 4 + 3][row] = v.w;
        }
        // stage W tile (32x128)
#pragma unroll
        for (int t = 0; t < 4; t++) {
            int p = tid + t * 256;     // 0..1023
            int k = p >> 5;            // 0..31
            int c4 = p & 31;           // 0..31
            *reinterpret_cast<float4*>(&Ws[k][c4 * 4]) =
                __ldg(reinterpret_cast<const float4*>(W + (size_t)(k0 + k) * 128 + c4 * 4));
        }
        __syncthreads();

#pragma unroll
        for (int kk = 0; kk < 32; kk++) {
            float4 w = *reinterpret_cast<const float4*>(&Ws[kk][c0]);
            u64 w0 = pack2(w.x, w.x);
            u64 w1 = pack2(w.y, w.y);
            u64 w2 = pack2(w.z, w.z);
            u64 w3 = pack2(w.w, w.w);
#pragma unroll
            for (int p = 0; p < 4; p++) {
                u64 a = *reinterpret_cast<const u64*>(&At[kk][r0 + 2 * p]);  // broadcast LDS.64
                acc[p][0] = fma2(a, w0, acc[p][0]);
                acc[p][1] = fma2(a, w1, acc[p][1]);
                acc[p][2] = fma2(a, w2, acc[p][2]);
                acc[p][3] = fma2(a, w3, acc[p][3]);
            }
        }
        __syncthreads();
    }

    float b0 = bias[c0 + 0], b1 = bias[c0 + 1], b2 = bias[c0 + 2], b3 = bias[c0 + 3];
#pragma unroll
    for (int p = 0; p < 4; p++) {
        float2 a0 = unpack2(acc[p][0]);
        float2 a1 = unpack2(acc[p][1]);
        float2 a2 = unpack2(acc[p][2]);
        float2 a3 = unpack2(acc[p][3]);
#pragma unroll
        for (int h = 0; h < 2; h++) {
            int gr = rowBase + r0 + 2 * p + h;
            if (gr < N_NODES) {
                float4 v;
                v.x = (h ? a0.y : a0.x) + b0;
                v.y = (h ? a1.y : a1.x) + b1;
                v.z = (h ? a2.y : a2.x) + b2;
                v.w = (h ? a3.y : a3.x) + b3;
                if (RELU) {
                    v.x = fmaxf(v.x, 0.f); v.y = fmaxf(v.y, 0.f);
                    v.z = fmaxf(v.z, 0.f); v.w = fmaxf(v.w, 0.f);
                }
                if (SCALE_OUT) {
                    float co = __ldg(&g_cout[gr]);
                    v.x *= co; v.y *= co; v.z *= co; v.w *= co;
                }
                if (POOL) {
                    int g = __ldg(&gid[gr]);
                    red_add_v4(g_gsum + (size_t)g * 128 + c0, v);
                } else {
                    *reinterpret_cast<float4*>(C + (size_t)gr * 128 + c0) = v;
                }
            }
        }
    }
}

// ---------------- fused MLP head (16 graphs per block) -----------------------
__global__ __launch_bounds__(256)
void mlp_kernel(const float* __restrict__ fg,
                const float* __restrict__ Wl1, const float* __restrict__ bl1,
                const float* __restrict__ Wl2, const float* __restrict__ bl2,
                const float* __restrict__ Wl3, const float* __restrict__ bl3,
                float* __restrict__ out) {
    __shared__ float in_s[16][132];
    __shared__ float h_s[16][256];

    int tid = threadIdx.x;
    int gBase = blockIdx.x * 16;

    for (int idx = tid; idx < 16 * 128; idx += 256) {
        int gl = idx >> 7, f = idx & 127;
        int g = gBase + gl;
        float c = (float)g_gcnt[g];
        in_s[gl][f] = g_gsum[(size_t)g * 128 + f] / fmaxf(c, 1.0f);
    }
    for (int idx = tid; idx < 16 * 3; idx += 256) {
        int gl = idx / 3, f = idx % 3;
        in_s[gl][128 + f] = fg[(size_t)(gBase + gl) * 3 + f];
    }
    __syncthreads();

    float acc[16];
    {
        float b = bl1[tid];
#pragma unroll
        for (int g = 0; g < 16; g++) acc[g] = b;
        for (int i = 0; i < 131; i++) {
            float w = __ldg(&Wl1[(size_t)i * 256 + tid]);
#pragma unroll
            for (int g = 0; g < 16; g++) acc[g] = fmaf(in_s[g][i], w, acc[g]);
        }
#pragma unroll
        for (int g = 0; g < 16; g++) h_s[g][tid] = fmaxf(acc[g], 0.f);
    }
    __syncthreads();
    {
        float b = bl2[tid];
#pragma unroll
        for (int g = 0; g < 16; g++) acc[g] = b;
        for (int i = 0; i < 256; i++) {
            float w = __ldg(&Wl2[(size_t)i * 256 + tid]);
#pragma unroll
            for (int g = 0; g < 16; g++) acc[g] = fmaf(h_s[g][i], w, acc[g]);
        }
        __syncthreads();
#pragma unroll
        for (int g = 0; g < 16; g++) h_s[g][tid] = fmaxf(acc[g], 0.f);
    }
    __syncthreads();
    {
        int g = tid >> 4;
        int lane = tid & 15;
        float s = 0.f;
        for (int j = lane; j < 256; j += 16) s += h_s[g][j] * __ldg(&Wl3[j]);
#pragma unroll
        for (int off = 8; off > 0; off >>= 1)
            s += __shfl_down_sync(0xFFFFFFFFu, s, off, 16);
        if (lane == 0) out[gBase + g] = s + bl3[0];
    }
}

// ---------------- launch -----------------------------------------------------
extern "C" void kernel_launch(void* const* d_in, const int* in_sizes, int n_in,
                              void* d_out, int out_size) {
    const float* feats_node  = (const float*)d_in[0];
    const float* feats_graph = (const float*)d_in[1];
    const float* W1 = (const float*)d_in[2];
    const float* b1 = (const float*)d_in[3];
    const float* W2 = (const float*)d_in[4];
    const float* b2 = (const float*)d_in[5];
    const float* W3 = (const float*)d_in[6];
    const float* b3 = (const float*)d_in[7];
    const float* Wl1 = (const float*)d_in[8];
    const float* bl1 = (const float*)d_in[9];
    const float* Wl2 = (const float*)d_in[10];
    const float* bl2 = (const float*)d_in[11];
    const float* Wl3 = (const float*)d_in[12];
    const float* bl3 = (const float*)d_in[13];
    const int* src = (const int*)d_in[14];
    const int* dst = (const int*)d_in[15];
    const int* gid = (const int*)d_in[16];
    float* out = (float*)d_out;

    void *p_agg, *p_x, *p_y;
    cudaGetSymbolAddress(&p_agg, g_agg);
    cudaGetSymbolAddress(&p_x, g_x);
    cudaGetSymbolAddress(&p_y, g_y);
    float* agg = (float*)p_agg;
    float* xb  = (float*)p_x;
    float* yb  = (float*)p_y;

    // --- graph preprocessing: degrees, CSR by dst, coeffs ---
    zero_misc_kernel<<<(N_GRAPHS * HIDDEN + 255) / 256, 256>>>();
    degree_kernel<<<(N_EDGES + 255) / 256, 256>>>(src, dst);
    scan_block_kernel<<<SCAN_NB, SCAN_BS>>>();
    scan_sums_kernel<<<1, 32>>>();
    scan_add_coeff_kernel<<<SCAN_NB, SCAN_BS>>>(gid);
    fill_kernel<<<(N_EDGES + 255) / 256, 256>>>(src, dst);

    const int gemm_blocks = (N_NODES + 63) / 64;

    // ---- layer 1: pull (c_out applied per edge), GEMM 64->128, relu, *c_out
    pull_kernel<IN_FEATS, true><<<(N_NODES * (IN_FEATS / 4) + 255) / 256, 256>>>(feats_node);
    gemm_kernel<IN_FEATS, true, true, false><<<gemm_blocks, 256>>>(agg, W1, b1, xb, gid);

    // ---- layer 2: pull (input pre-scaled), GEMM 128->128, relu, *c_out
    pull_kernel<HIDDEN, false><<<(N_NODES * (HIDDEN / 4) + 255) / 256, 256>>>(xb);
    gemm_kernel<HIDDEN, true, true, false><<<gemm_blocks, 256>>>(agg, W2, b2, yb, gid);

    // ---- layer 3: pull, GEMM 128->128 (no relu), fused mean-pool RED
    pull_kernel<HIDDEN, false><<<(N_NODES * (HIDDEN / 4) + 255) / 256, 256>>>(yb);
    gemm_kernel<HIDDEN, false, false, true><<<gemm_blocks, 256>>>(agg, W3, b3, nullptr, gid);

    // ---- MLP head ----
    mlp_kernel<<<N_GRAPHS / 16, 256>>>(feats_graph, Wl1, bl1, Wl2, bl2, Wl3, bl3, out);
}